// round 1
// baseline (speedup 1.0000x reference)
#include <cuda_runtime.h>
#include <cstdint>

// ---------------------------------------------------------------------------
// DistributedAttention: B=2, S=4096, H=1024 fp32.
//   q = x@Wq^T+bq ; k = x@Wk^T+bk ; v = x@Wv^T+bv          (NT GEMMs, M=8192,N=1024,K=1024)
//   scores = q@k^T / 8                                      (batched NT, M=N=4096,K=1024)
//   weights = softmax(scores, axis=-1)                      (row softmax, 8192 rows x 4096)
//   attn = weights@v                                        (batched NN, M=4096,N=1024,K=4096)
//   out = attn@Wo^T + bo                                    (NT, M=8192,N=1024,K=1024)
// ---------------------------------------------------------------------------

#define TILE 128
#define TK   16

// Scratch (no cudaMalloc allowed): ~235 MB of __device__ globals.
__device__ float g_q[2u * 4096u * 1024u];   // later reused for attn output
__device__ float g_k[2u * 4096u * 1024u];
__device__ float g_v[2u * 4096u * 1024u];
__device__ float g_s[2ull * 4096ull * 4096ull];

// ---------------------------------------------------------------------------
// 128x128x16 fp32 GEMM, 256 threads, 8x8 microtile per thread (4+4 split
// fragments for conflict-free LDS.128). BT=true: B is [N,K] row-major (NT).
// BT=false: B is [K,N] row-major (NN). All dims multiples of 128/16 here,
// so no bounds checks. blockIdx.z = batch with explicit strides.
// ---------------------------------------------------------------------------
template <bool BT, bool BIAS>
__global__ void __launch_bounds__(256, 2)
gemm128(const float* __restrict__ A, const float* __restrict__ Bm,
        const float* __restrict__ bias, float* __restrict__ C,
        int M, int N, int K, float alpha,
        long long sA, long long sB, long long sC)
{
    A  += (long long)blockIdx.z * sA;
    Bm += (long long)blockIdx.z * sB;
    C  += (long long)blockIdx.z * sC;

    const int bm = blockIdx.y * TILE;
    const int bn = blockIdx.x * TILE;
    const int t  = threadIdx.x;

    // Padded pitch 132 reduces STS bank conflicts on the transposed A store.
    __shared__ float As[TK][TILE + 4];
    __shared__ float Bs[TK][TILE + 4];

    const int u = t >> 4;   // 0..15 -> row fragment group
    const int w = t & 15;   // 0..15 -> col fragment group

    float acc[8][8];
#pragma unroll
    for (int i = 0; i < 8; i++)
#pragma unroll
        for (int j = 0; j < 8; j++) acc[i][j] = 0.f;

    for (int k0 = 0; k0 < K; k0 += TK) {
        // ---- load A tile (128 rows x 16 k), transpose into As[k][m] ----
#pragma unroll
        for (int i = 0; i < 2; i++) {
            int idx = t + i * 256;          // 0..511
            int row = idx >> 2;             // 0..127
            int kq  = (idx & 3) * 4;        // 0,4,8,12
            float4 av = *(const float4*)&A[(long long)(bm + row) * K + k0 + kq];
            As[kq + 0][row] = av.x;
            As[kq + 1][row] = av.y;
            As[kq + 2][row] = av.z;
            As[kq + 3][row] = av.w;
        }
        // ---- load B tile ----
        if (BT) {
#pragma unroll
            for (int i = 0; i < 2; i++) {
                int idx = t + i * 256;
                int row = idx >> 2;         // n within tile
                int kq  = (idx & 3) * 4;
                float4 bv = *(const float4*)&Bm[(long long)(bn + row) * K + k0 + kq];
                Bs[kq + 0][row] = bv.x;
                Bs[kq + 1][row] = bv.y;
                Bs[kq + 2][row] = bv.z;
                Bs[kq + 3][row] = bv.w;
            }
        } else {
#pragma unroll
            for (int i = 0; i < 2; i++) {
                int idx  = t + i * 256;
                int krow = idx >> 5;        // 0..15
                int nc   = (idx & 31) * 4;  // 0..124
                float4 bv = *(const float4*)&Bm[(long long)(k0 + krow) * N + bn + nc];
                *(float4*)&Bs[krow][nc] = bv;
            }
        }
        __syncthreads();

        // ---- 16 k-steps of 8x8 FMAs ----
#pragma unroll
        for (int k = 0; k < TK; k++) {
            float a[8], b[8];
            *(float4*)&a[0] = *(const float4*)&As[k][4 * u];
            *(float4*)&a[4] = *(const float4*)&As[k][64 + 4 * u];
            *(float4*)&b[0] = *(const float4*)&Bs[k][4 * w];
            *(float4*)&b[4] = *(const float4*)&Bs[k][64 + 4 * w];
#pragma unroll
            for (int i = 0; i < 8; i++)
#pragma unroll
                for (int j = 0; j < 8; j++) acc[i][j] += a[i] * b[j];
        }
        __syncthreads();
    }

    // ---- epilogue: C = alpha*acc (+ bias) ----
#pragma unroll
    for (int i = 0; i < 8; i++) {
        int rm = bm + ((i < 4) ? (4 * u + i) : (64 + 4 * u + (i - 4)));
#pragma unroll
        for (int jq = 0; jq < 2; jq++) {
            int cn = bn + ((jq == 0) ? (4 * w) : (64 + 4 * w));
            float4 o;
            o.x = alpha * acc[i][jq * 4 + 0];
            o.y = alpha * acc[i][jq * 4 + 1];
            o.z = alpha * acc[i][jq * 4 + 2];
            o.w = alpha * acc[i][jq * 4 + 3];
            if (BIAS) {
                float4 bb = *(const float4*)&bias[cn];
                o.x += bb.x; o.y += bb.y; o.z += bb.z; o.w += bb.w;
            }
            *(float4*)&C[(long long)rm * N + cn] = o;
        }
    }
}

// ---------------------------------------------------------------------------
// In-place row softmax: one 256-thread block per row of 4096 floats.
// Each thread keeps 16 elements in registers (single global read + write).
// ---------------------------------------------------------------------------
__global__ void __launch_bounds__(256)
softmax_rows4096(float* __restrict__ S)
{
    float* row = S + (size_t)blockIdx.x * 4096u;
    const int t    = threadIdx.x;
    const int lane = t & 31;
    const int wid  = t >> 5;

    __shared__ float red[8];

    float v[16];
    float m = -3.4e38f;
    float4* r4 = (float4*)row;
#pragma unroll
    for (int i = 0; i < 4; i++) {
        float4 val = r4[t + i * 256];
        v[4 * i + 0] = val.x; v[4 * i + 1] = val.y;
        v[4 * i + 2] = val.z; v[4 * i + 3] = val.w;
        m = fmaxf(m, fmaxf(fmaxf(val.x, val.y), fmaxf(val.z, val.w)));
    }
    // block max
#pragma unroll
    for (int o = 16; o > 0; o >>= 1) m = fmaxf(m, __shfl_xor_sync(0xffffffffu, m, o));
    if (lane == 0) red[wid] = m;
    __syncthreads();
    if (t == 0) {
        float mm = red[0];
#pragma unroll
        for (int i = 1; i < 8; i++) mm = fmaxf(mm, red[i]);
        red[0] = mm;
    }
    __syncthreads();
    m = red[0];
    __syncthreads();

    float s = 0.f;
#pragma unroll
    for (int i = 0; i < 16; i++) {
        v[i] = __expf(v[i] - m);
        s += v[i];
    }
    // block sum
#pragma unroll
    for (int o = 16; o > 0; o >>= 1) s += __shfl_xor_sync(0xffffffffu, s, o);
    if (lane == 0) red[wid] = s;
    __syncthreads();
    if (t == 0) {
        float ss = red[0];
#pragma unroll
        for (int i = 1; i < 8; i++) ss += red[i];
        red[0] = ss;
    }
    __syncthreads();
    float inv = 1.0f / red[0];

#pragma unroll
    for (int i = 0; i < 4; i++) {
        float4 val;
        val.x = v[4 * i + 0] * inv; val.y = v[4 * i + 1] * inv;
        val.z = v[4 * i + 2] * inv; val.w = v[4 * i + 3] * inv;
        r4[t + i * 256] = val;
    }
}

// ---------------------------------------------------------------------------
extern "C" void kernel_launch(void* const* d_in, const int* in_sizes, int n_in,
                              void* d_out, int out_size)
{
    const float* x  = (const float*)d_in[0];
    const float* Wq = (const float*)d_in[1];
    const float* bq = (const float*)d_in[2];
    const float* Wk = (const float*)d_in[3];
    const float* bk = (const float*)d_in[4];
    const float* Wv = (const float*)d_in[5];
    const float* bv = (const float*)d_in[6];
    const float* Wo = (const float*)d_in[7];
    const float* bo = (const float*)d_in[8];
    float* out = (float*)d_out;

    float *q, *k, *v, *s;
    cudaGetSymbolAddress((void**)&q, g_q);
    cudaGetSymbolAddress((void**)&k, g_k);
    cudaGetSymbolAddress((void**)&v, g_v);
    cudaGetSymbolAddress((void**)&s, g_s);

    const int B = 2, S = 4096, H = 1024;
    const long long qkvStride = (long long)S * H;      // per-batch q/k/v
    const long long sStride   = (long long)S * S;      // per-batch scores

    dim3 blk(256);

    // Q/K/V projections: M=8192, N=1024, K=1024 (NT, bias)
    dim3 gProj(H / TILE, (B * S) / TILE, 1);
    gemm128<true, true><<<gProj, blk>>>(x, Wq, bq, q, B * S, H, H, 1.0f, 0, 0, 0);
    gemm128<true, true><<<gProj, blk>>>(x, Wk, bk, k, B * S, H, H, 1.0f, 0, 0, 0);
    gemm128<true, true><<<gProj, blk>>>(x, Wv, bv, v, B * S, H, H, 1.0f, 0, 0, 0);

    // scores = q k^T / sqrt(64): batched NT, M=N=4096, K=1024
    dim3 gSc(S / TILE, S / TILE, B);
    gemm128<true, false><<<gSc, blk>>>(q, k, nullptr, s, S, S, H, 0.125f,
                                       qkvStride, qkvStride, sStride);

    // softmax over last dim
    softmax_rows4096<<<B * S, blk>>>(s);

    // attn = weights @ v: batched NN, M=4096, N=1024, K=4096 (writes into g_q)
    dim3 gAt(H / TILE, S / TILE, B);
    gemm128<false, false><<<gAt, blk>>>(s, v, nullptr, q, S, H, S, 1.0f,
                                        sStride, qkvStride, qkvStride);

    // out = attn @ Wo^T + bo: NT, M=8192, N=1024, K=1024
    gemm128<true, true><<<gProj, blk>>>(q, Wo, bo, out, B * S, H, H, 1.0f, 0, 0, 0);
}

// round 5
// speedup vs baseline: 2.4281x; 2.4281x over previous
#include <cuda_runtime.h>
#include <cuda_bf16.h>
#include <cstdint>

// ---------------------------------------------------------------------------
// DistributedAttention, B=2, S=4096, H=1024 fp32.
// bf16x3 error-compensated mma.sync (a = hi + lo; hi*hi + hi*lo + lo*hi).
// All GEMMs NT: C[M,N] = alpha * A[M,K] @ B[N,K]^T (+bias).
// ---------------------------------------------------------------------------

#define BM 128
#define BN 128
#define KT 32
#define STAGES 4
#define APITCH 80                       // bytes per 32-bf16 row (5x16B -> bank-clean ldmatrix)
#define REG_BYTES (128 * APITCH)        // 10240 per operand component
#define STAGE_BYTES (4 * REG_BYTES)     // Ahi, Alo, Bhi, Blo = 40960
#define GEMM_SMEM (STAGES * STAGE_BYTES)  // 160KB

typedef __nv_bfloat16 bf16;

// fp32 scratch
__device__ float g_v[8388608];          // v projection (fp32, pre-transpose)
__device__ float g_s[33554432];         // scores (fp32)
// split (hi/lo bf16) scratch
__device__ bf16 g_xh[8388608],  g_xl[8388608];
__device__ bf16 g_wqh[1048576], g_wql[1048576];
__device__ bf16 g_wkh[1048576], g_wkl[1048576];
__device__ bf16 g_wvh[1048576], g_wvl[1048576];
__device__ bf16 g_woh[1048576], g_wol[1048576];
__device__ bf16 g_qh[8388608],  g_ql[8388608];
__device__ bf16 g_kh[8388608],  g_kl[8388608];
__device__ bf16 g_vth[8388608], g_vtl[8388608];
__device__ bf16 g_wh[33554432], g_wl[33554432];   // softmax weights
__device__ bf16 g_ah[8388608],  g_al[8388608];    // attn output

__device__ __forceinline__ uint32_t smem_u32(const void* p) {
    uint32_t a;
    asm("{ .reg .u64 t; cvta.to.shared.u64 t, %1; cvt.u32.u64 %0, t; }" : "=r"(a) : "l"(p));
    return a;
}
__device__ __forceinline__ void cp16(uint32_t dst, const void* src) {
    asm volatile("cp.async.cg.shared.global [%0], [%1], 16;" :: "r"(dst), "l"(src));
}

#define LDSM4(r, addr) \
    asm volatile("ldmatrix.sync.aligned.m8n8.x4.shared.b16 {%0,%1,%2,%3}, [%4];" \
                 : "=r"((r)[0]), "=r"((r)[1]), "=r"((r)[2]), "=r"((r)[3]) : "r"(addr))
#define LDSM2(r, addr) \
    asm volatile("ldmatrix.sync.aligned.m8n8.x2.shared.b16 {%0,%1}, [%2];" \
                 : "=r"((r)[0]), "=r"((r)[1]) : "r"(addr))

__device__ __forceinline__ void mma16(float* c, const uint32_t* a, const uint32_t* b) {
    asm volatile(
        "mma.sync.aligned.m16n8k16.row.col.f32.bf16.bf16.f32 "
        "{%0,%1,%2,%3}, {%4,%5,%6,%7}, {%8,%9}, {%0,%1,%2,%3};"
        : "+f"(c[0]), "+f"(c[1]), "+f"(c[2]), "+f"(c[3])
        : "r"(a[0]), "r"(a[1]), "r"(a[2]), "r"(a[3]), "r"(b[0]), "r"(b[1]));
}

// split pair (a=low element, b=high element) into packed bf16x2 hi / lo words
__device__ __forceinline__ void split2(float a, float b, uint32_t& hi2, uint32_t& lo2) {
    uint32_t ua = __float_as_uint(a) & 0xFFFF0000u;
    uint32_t ub = __float_as_uint(b) & 0xFFFF0000u;
    hi2 = (ua >> 16) | ub;
    __nv_bfloat162 l2 = __floats2bfloat162_rn(a - __uint_as_float(ua),
                                              b - __uint_as_float(ub));
    lo2 = *reinterpret_cast<uint32_t*>(&l2);
}

// ---------------------------------------------------------------------------
// bf16x3 NT GEMM. 256 threads, warp grid 2(m) x 4(n), warp tile 64x32.
// ---------------------------------------------------------------------------
template <bool BIAS, bool SPLIT_OUT>
__global__ void __launch_bounds__(256, 1)
gemm_b3(const bf16* __restrict__ Ah, const bf16* __restrict__ Al,
        const bf16* __restrict__ Bh, const bf16* __restrict__ Bl,
        const float* __restrict__ bias, float* __restrict__ C,
        bf16* __restrict__ Chi, bf16* __restrict__ Clo,
        int M, int N, int K, float alpha,
        long long sA, long long sB, long long sC)
{
    extern __shared__ char sm[];
    const uint32_t smb = smem_u32(sm);

    Ah += (long long)blockIdx.z * sA;  Al += (long long)blockIdx.z * sA;
    Bh += (long long)blockIdx.z * sB;  Bl += (long long)blockIdx.z * sB;
    if (SPLIT_OUT) { Chi += (long long)blockIdx.z * sC; Clo += (long long)blockIdx.z * sC; }
    else           { C   += (long long)blockIdx.z * sC; }

    const int bm = blockIdx.y * BM;
    const int bn = blockIdx.x * BN;
    const int t  = threadIdx.x;
    const int wid  = t >> 5;
    const int lane = t & 31;
    const int g    = lane >> 2;
    const int tig  = lane & 3;
    const int wm = (wid >> 2) * 64;
    const int wn = (wid & 3) * 32;

    const bf16* Abh = Ah + (long long)bm * K;
    const bf16* Abl = Al + (long long)bm * K;
    const bf16* Bbh = Bh + (long long)bn * K;
    const bf16* Bbl = Bl + (long long)bn * K;
    const int T = K / KT;

    auto load_tile = [&](int kt, int s) {
        uint32_t st = smb + s * STAGE_BYTES;
        const bf16* ah = Abh + kt * KT;
        const bf16* al = Abl + kt * KT;
        const bf16* bh = Bbh + kt * KT;
        const bf16* bl = Bbl + kt * KT;
#pragma unroll
        for (int j = 0; j < 2; j++) {
            int id = t + j * 256;          // 0..511
            int r  = id >> 2;              // 0..127
            int c  = id & 3;               // 16B chunk (8 bf16)
            uint32_t dst = st + r * APITCH + c * 16;
            long long  src = (long long)r * K + c * 8;
            cp16(dst,                 ah + src);
            cp16(dst + REG_BYTES,     al + src);
            cp16(dst + 2 * REG_BYTES, bh + src);
            cp16(dst + 3 * REG_BYTES, bl + src);
        }
    };

#pragma unroll
    for (int p = 0; p < STAGES - 1; p++) {
        load_tile(p, p);
        asm volatile("cp.async.commit_group;" ::: "memory");
    }

    float acc[4][4][4];
#pragma unroll
    for (int mt = 0; mt < 4; mt++)
#pragma unroll
        for (int nt = 0; nt < 4; nt++)
#pragma unroll
            for (int r = 0; r < 4; r++) acc[mt][nt][r] = 0.f;

    // per-lane ldmatrix base addresses (row = lane&15 for A(x4), lane&7 for B(x2))
    const uint32_t a_off = (wm + (lane & 15)) * APITCH + (lane >> 4) * 16;
    const uint32_t b_off = 2 * REG_BYTES + (wn + (lane & 7)) * APITCH + ((lane >> 3) & 1) * 16;

    for (int kt = 0; kt < T; kt++) {
        int s = kt & (STAGES - 1);
        asm volatile("cp.async.wait_group 2;" ::: "memory");
        __syncthreads();

        const uint32_t st = smb + s * STAGE_BYTES;
        const uint32_t ab = st + a_off;
        const uint32_t bb = st + b_off;

#pragma unroll
        for (int ks = 0; ks < 2; ks++) {       // two k=16 steps per KT=32
            uint32_t ah[4][4], al[4][4], bh[4][2], bl[4][2];
#pragma unroll
            for (int mt = 0; mt < 4; mt++) {
                LDSM4(ah[mt], ab + mt * (16 * APITCH) + ks * 32);
                LDSM4(al[mt], ab + REG_BYTES + mt * (16 * APITCH) + ks * 32);
            }
#pragma unroll
            for (int nt = 0; nt < 4; nt++) {
                LDSM2(bh[nt], bb + nt * (8 * APITCH) + ks * 32);
                LDSM2(bl[nt], bb + REG_BYTES + nt * (8 * APITCH) + ks * 32);
            }
            // term-outer order: same-acc MMAs are 16 apart (no RAW stall chain)
#pragma unroll
            for (int mt = 0; mt < 4; mt++)
#pragma unroll
                for (int nt = 0; nt < 4; nt++) mma16(acc[mt][nt], ah[mt], bh[nt]);
#pragma unroll
            for (int mt = 0; mt < 4; mt++)
#pragma unroll
                for (int nt = 0; nt < 4; nt++) mma16(acc[mt][nt], ah[mt], bl[nt]);
#pragma unroll
            for (int mt = 0; mt < 4; mt++)
#pragma unroll
                for (int nt = 0; nt < 4; nt++) mma16(acc[mt][nt], al[mt], bh[nt]);
        }

        int pf = kt + STAGES - 1;
        if (pf < T) load_tile(pf, pf & (STAGES - 1));
        asm volatile("cp.async.commit_group;" ::: "memory");
    }

    // ---- epilogue ----
#pragma unroll
    for (int mt = 0; mt < 4; mt++) {
        int r0 = bm + wm + mt * 16 + g;
#pragma unroll
        for (int nt = 0; nt < 4; nt++) {
            int col = bn + wn + nt * 8 + tig * 2;
            float2 v01, v23;
            v01.x = alpha * acc[mt][nt][0];
            v01.y = alpha * acc[mt][nt][1];
            v23.x = alpha * acc[mt][nt][2];
            v23.y = alpha * acc[mt][nt][3];
            if (BIAS) {
                float2 bb = *(const float2*)&bias[col];
                v01.x += bb.x; v01.y += bb.y;
                v23.x += bb.x; v23.y += bb.y;
            }
            if (SPLIT_OUT) {
                uint32_t h2, l2;
                split2(v01.x, v01.y, h2, l2);
                *(uint32_t*)&Chi[(long long)r0 * N + col] = h2;
                *(uint32_t*)&Clo[(long long)r0 * N + col] = l2;
                split2(v23.x, v23.y, h2, l2);
                *(uint32_t*)&Chi[(long long)(r0 + 8) * N + col] = h2;
                *(uint32_t*)&Clo[(long long)(r0 + 8) * N + col] = l2;
            } else {
                *(float2*)&C[(long long)r0 * N + col] = v01;
                *(float2*)&C[(long long)(r0 + 8) * N + col] = v23;
            }
        }
    }
}

// ---------------------------------------------------------------------------
// fp32 -> (hi, lo) bf16 split, 4 elts/thread
// ---------------------------------------------------------------------------
__global__ void __launch_bounds__(256)
split_f32(const float* __restrict__ in, bf16* __restrict__ hi, bf16* __restrict__ lo, int n4)
{
    int i = blockIdx.x * 256 + threadIdx.x;
    if (i >= n4) return;
    float4 v = ((const float4*)in)[i];
    uint32_t h2, l2;
    split2(v.x, v.y, h2, l2);
    ((uint32_t*)hi)[i * 2]     = h2;
    ((uint32_t*)lo)[i * 2]     = l2;
    split2(v.z, v.w, h2, l2);
    ((uint32_t*)hi)[i * 2 + 1] = h2;
    ((uint32_t*)lo)[i * 2 + 1] = l2;
}

// ---------------------------------------------------------------------------
// v [4096,1024] -> vT [1024,4096] per batch, split to hi/lo at write
// ---------------------------------------------------------------------------
__global__ void __launch_bounds__(256)
transpose_v_split(const float* __restrict__ in, bf16* __restrict__ oh, bf16* __restrict__ ol)
{
    __shared__ float tb[32][33];
    in += (long long)blockIdx.z * 4096 * 1024;
    oh += (long long)blockIdx.z * 4096 * 1024;
    ol += (long long)blockIdx.z * 4096 * 1024;
    int x = blockIdx.x * 32 + threadIdx.x;
    int y = blockIdx.y * 32;
#pragma unroll
    for (int j = 0; j < 32; j += 8)
        tb[threadIdx.y + j][threadIdx.x] = in[(long long)(y + threadIdx.y + j) * 1024 + x];
    __syncthreads();
    int ox = blockIdx.y * 32 + threadIdx.x;
    int oy = blockIdx.x * 32;
#pragma unroll
    for (int j = 0; j < 32; j += 8) {
        float a = tb[threadIdx.x][threadIdx.y + j];
        uint32_t ua = __float_as_uint(a) & 0xFFFF0000u;
        long long idx = (long long)(oy + threadIdx.y + j) * 4096 + ox;
        ((uint16_t*)oh)[idx] = (uint16_t)(ua >> 16);
        ol[idx] = __float2bfloat16_rn(a - __uint_as_float(ua));
    }
}

// ---------------------------------------------------------------------------
// Row softmax over 4096 floats; writes split bf16 weights.
// ---------------------------------------------------------------------------
__global__ void __launch_bounds__(256)
softmax_split(const float* __restrict__ S, bf16* __restrict__ wh, bf16* __restrict__ wl)
{
    const float* row = S + (size_t)blockIdx.x * 4096u;
    const size_t ob = (size_t)blockIdx.x * 4096u;
    const int t = threadIdx.x, lane = t & 31, wid = t >> 5;
    __shared__ float red[8];

    float v[16];
    float m = -3.4e38f;
    const float4* r4 = (const float4*)row;
#pragma unroll
    for (int i = 0; i < 4; i++) {
        float4 val = r4[t + i * 256];
        v[4 * i + 0] = val.x; v[4 * i + 1] = val.y;
        v[4 * i + 2] = val.z; v[4 * i + 3] = val.w;
        m = fmaxf(m, fmaxf(fmaxf(val.x, val.y), fmaxf(val.z, val.w)));
    }
#pragma unroll
    for (int o = 16; o > 0; o >>= 1) m = fmaxf(m, __shfl_xor_sync(0xffffffffu, m, o));
    if (lane == 0) red[wid] = m;
    __syncthreads();
    if (t == 0) {
        float mm = red[0];
#pragma unroll
        for (int i = 1; i < 8; i++) mm = fmaxf(mm, red[i]);
        red[0] = mm;
    }
    __syncthreads();
    m = red[0];
    __syncthreads();

    float s = 0.f;
#pragma unroll
    for (int i = 0; i < 16; i++) { v[i] = __expf(v[i] - m); s += v[i]; }
#pragma unroll
    for (int o = 16; o > 0; o >>= 1) s += __shfl_xor_sync(0xffffffffu, s, o);
    if (lane == 0) red[wid] = s;
    __syncthreads();
    if (t == 0) {
        float ss = red[0];
#pragma unroll
        for (int i = 1; i < 8; i++) ss += red[i];
        red[0] = ss;
    }
    __syncthreads();
    float inv = 1.0f / red[0];

#pragma unroll
    for (int i = 0; i < 4; i++) {
        size_t base = ob + (size_t)(t + i * 256) * 4;
        uint32_t h2, l2;
        split2(v[4 * i + 0] * inv, v[4 * i + 1] * inv, h2, l2);
        *(uint32_t*)&wh[base]     = h2;
        *(uint32_t*)&wl[base]     = l2;
        split2(v[4 * i + 2] * inv, v[4 * i + 3] * inv, h2, l2);
        *(uint32_t*)&wh[base + 2] = h2;
        *(uint32_t*)&wl[base + 2] = l2;
    }
}

// ---------------------------------------------------------------------------
extern "C" void kernel_launch(void* const* d_in, const int* in_sizes, int n_in,
                              void* d_out, int out_size)
{
    const float* x  = (const float*)d_in[0];
    const float* Wq = (const float*)d_in[1];
    const float* bq = (const float*)d_in[2];
    const float* Wk = (const float*)d_in[3];
    const float* bk = (const float*)d_in[4];
    const float* Wv = (const float*)d_in[5];
    const float* bv = (const float*)d_in[6];
    const float* Wo = (const float*)d_in[7];
    const float* bo = (const float*)d_in[8];
    float* out = (float*)d_out;

    float *v, *s;
    bf16 *xh, *xl, *wqh, *wql, *wkh, *wkl, *wvh, *wvl, *woh, *wol;
    bf16 *qh, *ql, *kh, *kl, *vth, *vtl, *wh, *wl, *ah, *al;
    cudaGetSymbolAddress((void**)&v,   g_v);
    cudaGetSymbolAddress((void**)&s,   g_s);
    cudaGetSymbolAddress((void**)&xh,  g_xh);  cudaGetSymbolAddress((void**)&xl,  g_xl);
    cudaGetSymbolAddress((void**)&wqh, g_wqh); cudaGetSymbolAddress((void**)&wql, g_wql);
    cudaGetSymbolAddress((void**)&wkh, g_wkh); cudaGetSymbolAddress((void**)&wkl, g_wkl);
    cudaGetSymbolAddress((void**)&wvh, g_wvh); cudaGetSymbolAddress((void**)&wvl, g_wvl);
    cudaGetSymbolAddress((void**)&woh, g_woh); cudaGetSymbolAddress((void**)&wol, g_wol);
    cudaGetSymbolAddress((void**)&qh,  g_qh);  cudaGetSymbolAddress((void**)&ql,  g_ql);
    cudaGetSymbolAddress((void**)&kh,  g_kh);  cudaGetSymbolAddress((void**)&kl,  g_kl);
    cudaGetSymbolAddress((void**)&vth, g_vth); cudaGetSymbolAddress((void**)&vtl, g_vtl);
    cudaGetSymbolAddress((void**)&wh,  g_wh);  cudaGetSymbolAddress((void**)&wl,  g_wl);
    cudaGetSymbolAddress((void**)&ah,  g_ah);  cudaGetSymbolAddress((void**)&al,  g_al);

    cudaFuncSetAttribute(gemm_b3<true,  true >, cudaFuncAttributeMaxDynamicSharedMemorySize, GEMM_SMEM);
    cudaFuncSetAttribute(gemm_b3<true,  false>, cudaFuncAttributeMaxDynamicSharedMemorySize, GEMM_SMEM);
    cudaFuncSetAttribute(gemm_b3<false, true >, cudaFuncAttributeMaxDynamicSharedMemorySize, GEMM_SMEM);
    cudaFuncSetAttribute(gemm_b3<false, false>, cudaFuncAttributeMaxDynamicSharedMemorySize, GEMM_SMEM);

    const int B = 2, S = 4096, H = 1024;
    const long long qkv = (long long)S * H;
    const long long ss  = (long long)S * S;
    dim3 blk(256);

    // split inputs
    split_f32<<<(B * S * H / 4 + 255) / 256, blk>>>(x,  xh,  xl,  B * S * H / 4);
    split_f32<<<(H * H / 4 + 255) / 256, blk>>>(Wq, wqh, wql, H * H / 4);
    split_f32<<<(H * H / 4 + 255) / 256, blk>>>(Wk, wkh, wkl, H * H / 4);
    split_f32<<<(H * H / 4 + 255) / 256, blk>>>(Wv, wvh, wvl, H * H / 4);
    split_f32<<<(H * H / 4 + 255) / 256, blk>>>(Wo, woh, wol, H * H / 4);

    // Q/K projections -> split; V projection -> fp32 (for transpose)
    dim3 gProj(H / BN, (B * S) / BM, 1);
    gemm_b3<true, true ><<<gProj, blk, GEMM_SMEM>>>(xh, xl, wqh, wql, bq, nullptr, qh, ql,
                                                    B * S, H, H, 1.0f, 0, 0, 0);
    gemm_b3<true, true ><<<gProj, blk, GEMM_SMEM>>>(xh, xl, wkh, wkl, bk, nullptr, kh, kl,
                                                    B * S, H, H, 1.0f, 0, 0, 0);
    gemm_b3<true, false><<<gProj, blk, GEMM_SMEM>>>(xh, xl, wvh, wvl, bv, v, nullptr, nullptr,
                                                    B * S, H, H, 1.0f, 0, 0, 0);

    // scores = q @ k^T / 8 (fp32 out)
    dim3 gSc(S / BN, S / BM, B);
    gemm_b3<false, false><<<gSc, blk, GEMM_SMEM>>>(qh, ql, kh, kl, nullptr, s, nullptr, nullptr,
                                                   S, S, H, 0.125f, qkv, qkv, ss);

    // vT split
    dim3 gT(1024 / 32, 4096 / 32, B);
    transpose_v_split<<<gT, dim3(32, 8)>>>(v, vth, vtl);

    // softmax -> split weights
    softmax_split<<<B * S, blk>>>(s, wh, wl);

    // attn = weights @ vT^T -> split
    dim3 gAt(H / BN, S / BM, B);
    gemm_b3<false, true><<<gAt, blk, GEMM_SMEM>>>(wh, wl, vth, vtl, nullptr, nullptr, ah, al,
                                                  S, H, S, 1.0f, ss, qkv, qkv);

    // out = attn @ Wo^T + bo (fp32 out)
    gemm_b3<true, false><<<gProj, blk, GEMM_SMEM>>>(ah, al, woh, wol, bo, out, nullptr, nullptr,
                                                    B * S, H, H, 1.0f, 0, 0, 0);
}

// round 6
// speedup vs baseline: 2.6005x; 1.0710x over previous
#include <cuda_runtime.h>
#include <cuda_bf16.h>
#include <cstdint>

// ---------------------------------------------------------------------------
// DistributedAttention, B=2, S=4096, H=1024 fp32.
// bf16x3 error-compensated mma.sync (a = hi + lo; hi*hi + hi*lo + lo*hi).
// All GEMMs NT: C[M,N] = alpha * A[M,K] @ B[N,K]^T (+bias).
// R6: CTA 128x256, warp tile 64x64 (8 warps), paired-LDSM4 B frags,
//     3-stage cp.async pipeline. MMA:ldmatrix ratio 6:1.
// ---------------------------------------------------------------------------

#define BM 128
#define BN 256
#define KT 32
#define STAGES 3
#define APITCH 80                        // bytes per 32-bf16 row (5x16B, bank-clean)
#define REGA (128 * APITCH)              // 10240
#define REGB (256 * APITCH)              // 20480
#define STAGE_BYTES (2 * REGA + 2 * REGB)  // 61440
#define GEMM_SMEM (STAGES * STAGE_BYTES)   // 184320

typedef __nv_bfloat16 bf16;

// fp32 scratch
__device__ float g_v[8388608];          // v projection (fp32, pre-transpose)
__device__ float g_s[33554432];         // scores (fp32)
// split (hi/lo bf16) scratch
__device__ bf16 g_xh[8388608],  g_xl[8388608];
__device__ bf16 g_wqh[1048576], g_wql[1048576];
__device__ bf16 g_wkh[1048576], g_wkl[1048576];
__device__ bf16 g_wvh[1048576], g_wvl[1048576];
__device__ bf16 g_woh[1048576], g_wol[1048576];
__device__ bf16 g_qh[8388608],  g_ql[8388608];
__device__ bf16 g_kh[8388608],  g_kl[8388608];
__device__ bf16 g_vth[8388608], g_vtl[8388608];
__device__ bf16 g_wh[33554432], g_wl[33554432];   // softmax weights
__device__ bf16 g_ah[8388608],  g_al[8388608];    // attn output

__device__ __forceinline__ uint32_t smem_u32(const void* p) {
    uint32_t a;
    asm("{ .reg .u64 t; cvta.to.shared.u64 t, %1; cvt.u32.u64 %0, t; }" : "=r"(a) : "l"(p));
    return a;
}
__device__ __forceinline__ void cp16(uint32_t dst, const void* src) {
    asm volatile("cp.async.cg.shared.global [%0], [%1], 16;" :: "r"(dst), "l"(src));
}

#define LDSM4(r, addr) \
    asm volatile("ldmatrix.sync.aligned.m8n8.x4.shared.b16 {%0,%1,%2,%3}, [%4];" \
                 : "=r"((r)[0]), "=r"((r)[1]), "=r"((r)[2]), "=r"((r)[3]) : "r"(addr))

__device__ __forceinline__ void mma16(float* c, const uint32_t* a, const uint32_t* b) {
    asm volatile(
        "mma.sync.aligned.m16n8k16.row.col.f32.bf16.bf16.f32 "
        "{%0,%1,%2,%3}, {%4,%5,%6,%7}, {%8,%9}, {%0,%1,%2,%3};"
        : "+f"(c[0]), "+f"(c[1]), "+f"(c[2]), "+f"(c[3])
        : "r"(a[0]), "r"(a[1]), "r"(a[2]), "r"(a[3]), "r"(b[0]), "r"(b[1]));
}

// split pair (a=low element, b=high element) into packed bf16x2 hi / lo words
__device__ __forceinline__ void split2(float a, float b, uint32_t& hi2, uint32_t& lo2) {
    uint32_t ua = __float_as_uint(a) & 0xFFFF0000u;
    uint32_t ub = __float_as_uint(b) & 0xFFFF0000u;
    hi2 = (ua >> 16) | ub;
    __nv_bfloat162 l2 = __floats2bfloat162_rn(a - __uint_as_float(ua),
                                              b - __uint_as_float(ub));
    lo2 = *reinterpret_cast<uint32_t*>(&l2);
}

// ---------------------------------------------------------------------------
// bf16x3 NT GEMM. 256 threads, CTA 128x256, warp grid 2(m) x 4(n),
// warp tile 64x64. 3-stage cp.async pipeline.
// ---------------------------------------------------------------------------
template <bool BIAS, bool SPLIT_OUT>
__global__ void __launch_bounds__(256, 1)
gemm_b3(const bf16* __restrict__ Ah, const bf16* __restrict__ Al,
        const bf16* __restrict__ Bh, const bf16* __restrict__ Bl,
        const float* __restrict__ bias, float* __restrict__ C,
        bf16* __restrict__ Chi, bf16* __restrict__ Clo,
        int M, int N, int K, float alpha,
        long long sA, long long sB, long long sC)
{
    extern __shared__ char sm[];
    const uint32_t smb = smem_u32(sm);

    Ah += (long long)blockIdx.z * sA;  Al += (long long)blockIdx.z * sA;
    Bh += (long long)blockIdx.z * sB;  Bl += (long long)blockIdx.z * sB;
    if (SPLIT_OUT) { Chi += (long long)blockIdx.z * sC; Clo += (long long)blockIdx.z * sC; }
    else           { C   += (long long)blockIdx.z * sC; }

    const int bm = blockIdx.y * BM;
    const int bn = blockIdx.x * BN;
    const int t  = threadIdx.x;
    const int wid  = t >> 5;
    const int lane = t & 31;
    const int g    = lane >> 2;
    const int tig  = lane & 3;
    const int wm = (wid >> 2) * 64;   // 2 m-groups
    const int wn = (wid & 3) * 64;    // 4 n-groups

    const bf16* Abh = Ah + (long long)bm * K;
    const bf16* Abl = Al + (long long)bm * K;
    const bf16* Bbh = Bh + (long long)bn * K;
    const bf16* Bbl = Bl + (long long)bn * K;
    const int T = K / KT;

    auto load_tile = [&](int kt, int s) {
        uint32_t st = smb + s * STAGE_BYTES;
        // A: 1024 16B chunks (128 rows x 4 chunks x 2 comps)
#pragma unroll
        for (int j = 0; j < 4; j++) {
            int rem = t + (j & 1) * 256;           // 0..511
            int r = rem >> 2, c = rem & 3;
            const bf16* src = ((j >> 1) ? Abl : Abh) + kt * KT + (long long)r * K + c * 8;
            cp16(st + (j >> 1) * REGA + r * APITCH + c * 16, src);
        }
        // B: 2048 chunks (256 rows x 4 chunks x 2 comps)
#pragma unroll
        for (int j = 0; j < 8; j++) {
            int rem = t + (j & 3) * 256;           // 0..1023
            int r = rem >> 2, c = rem & 3;
            const bf16* src = ((j >> 2) ? Bbl : Bbh) + kt * KT + (long long)r * K + c * 8;
            cp16(st + 2 * REGA + (j >> 2) * REGB + r * APITCH + c * 16, src);
        }
    };

    load_tile(0, 0);
    asm volatile("cp.async.commit_group;" ::: "memory");
    load_tile(1, 1);
    asm volatile("cp.async.commit_group;" ::: "memory");

    float acc[4][8][4];
#pragma unroll
    for (int mt = 0; mt < 4; mt++)
#pragma unroll
        for (int nt = 0; nt < 8; nt++)
#pragma unroll
            for (int r = 0; r < 4; r++) acc[mt][nt][r] = 0.f;

    // ldmatrix lane addressing
    const uint32_t a_off = (wm + (lane & 15)) * APITCH + (lane >> 4) * 16;
    // paired B LDSM4: matrices [nt.k0, nt.k1, (nt+1).k0, (nt+1).k1]
    const uint32_t b_off = 2 * REGA + (wn + (lane >> 4) * 8 + (lane & 7)) * APITCH
                         + ((lane >> 3) & 1) * 16;

    int s_cur = 0;                       // kt % 3
    for (int kt = 0; kt < T; kt++) {
        asm volatile("cp.async.wait_group 1;" ::: "memory");
        __syncthreads();

        const uint32_t st = smb + s_cur * STAGE_BYTES;

#pragma unroll
        for (int ks = 0; ks < 2; ks++) {
            uint32_t ah[4][4], al[4][4];
#pragma unroll
            for (int mt = 0; mt < 4; mt++)
                LDSM4(ah[mt], st + a_off + mt * (16 * APITCH) + ks * 32);
#pragma unroll
            for (int mt = 0; mt < 4; mt++)
                LDSM4(al[mt], st + REGA + a_off + mt * (16 * APITCH) + ks * 32);

            uint32_t bh[2][4], bl[2][4];           // double-buffered nt-pairs
            LDSM4(bh[0], st + b_off + ks * 32);
            LDSM4(bl[0], st + REGB + b_off + ks * 32);
#pragma unroll
            for (int p = 0; p < 4; p++) {
                int cur = p & 1, nxt = cur ^ 1;
                if (p < 3) {
                    LDSM4(bh[nxt], st + b_off + (p + 1) * (16 * APITCH) + ks * 32);
                    LDSM4(bl[nxt], st + REGB + b_off + (p + 1) * (16 * APITCH) + ks * 32);
                }
#pragma unroll
                for (int mt = 0; mt < 4; mt++) {
                    mma16(acc[mt][2 * p],     ah[mt], &bh[cur][0]);
                    mma16(acc[mt][2 * p + 1], ah[mt], &bh[cur][2]);
                }
#pragma unroll
                for (int mt = 0; mt < 4; mt++) {
                    mma16(acc[mt][2 * p],     ah[mt], &bl[cur][0]);
                    mma16(acc[mt][2 * p + 1], ah[mt], &bl[cur][2]);
                }
#pragma unroll
                for (int mt = 0; mt < 4; mt++) {
                    mma16(acc[mt][2 * p],     al[mt], &bh[cur][0]);
                    mma16(acc[mt][2 * p + 1], al[mt], &bh[cur][2]);
                }
            }
        }

        int pf = kt + 2;
        if (pf < T) {
            int s_pf = s_cur;            // (kt+2) % 3 == (kt-1) % 3 slot being freed
            s_pf = s_pf + 2; if (s_pf >= 3) s_pf -= 3;
            load_tile(pf, s_pf);
        }
        asm volatile("cp.async.commit_group;" ::: "memory");
        s_cur = s_cur + 1; if (s_cur >= 3) s_cur -= 3;
    }

    // ---- epilogue ----
#pragma unroll
    for (int mt = 0; mt < 4; mt++) {
        int r0 = bm + wm + mt * 16 + g;
#pragma unroll
        for (int nt = 0; nt < 8; nt++) {
            int col = bn + wn + nt * 8 + tig * 2;
            float2 v01, v23;
            v01.x = alpha * acc[mt][nt][0];
            v01.y = alpha * acc[mt][nt][1];
            v23.x = alpha * acc[mt][nt][2];
            v23.y = alpha * acc[mt][nt][3];
            if (BIAS) {
                float2 bb = *(const float2*)&bias[col];
                v01.x += bb.x; v01.y += bb.y;
                v23.x += bb.x; v23.y += bb.y;
            }
            if (SPLIT_OUT) {
                uint32_t h2, l2;
                split2(v01.x, v01.y, h2, l2);
                *(uint32_t*)&Chi[(long long)r0 * N + col] = h2;
                *(uint32_t*)&Clo[(long long)r0 * N + col] = l2;
                split2(v23.x, v23.y, h2, l2);
                *(uint32_t*)&Chi[(long long)(r0 + 8) * N + col] = h2;
                *(uint32_t*)&Clo[(long long)(r0 + 8) * N + col] = l2;
            } else {
                *(float2*)&C[(long long)r0 * N + col] = v01;
                *(float2*)&C[(long long)(r0 + 8) * N + col] = v23;
            }
        }
    }
}

// ---------------------------------------------------------------------------
// fp32 -> (hi, lo) bf16 split, 4 elts/thread
// ---------------------------------------------------------------------------
__global__ void __launch_bounds__(256)
split_f32(const float* __restrict__ in, bf16* __restrict__ hi, bf16* __restrict__ lo, int n4)
{
    int i = blockIdx.x * 256 + threadIdx.x;
    if (i >= n4) return;
    float4 v = ((const float4*)in)[i];
    uint32_t h2, l2;
    split2(v.x, v.y, h2, l2);
    ((uint32_t*)hi)[i * 2]     = h2;
    ((uint32_t*)lo)[i * 2]     = l2;
    split2(v.z, v.w, h2, l2);
    ((uint32_t*)hi)[i * 2 + 1] = h2;
    ((uint32_t*)lo)[i * 2 + 1] = l2;
}

// ---------------------------------------------------------------------------
// v [4096,1024] -> vT [1024,4096] per batch, split to hi/lo at write
// ---------------------------------------------------------------------------
__global__ void __launch_bounds__(256)
transpose_v_split(const float* __restrict__ in, bf16* __restrict__ oh, bf16* __restrict__ ol)
{
    __shared__ float tb[32][33];
    in += (long long)blockIdx.z * 4096 * 1024;
    oh += (long long)blockIdx.z * 4096 * 1024;
    ol += (long long)blockIdx.z * 4096 * 1024;
    int x = blockIdx.x * 32 + threadIdx.x;
    int y = blockIdx.y * 32;
#pragma unroll
    for (int j = 0; j < 32; j += 8)
        tb[threadIdx.y + j][threadIdx.x] = in[(long long)(y + threadIdx.y + j) * 1024 + x];
    __syncthreads();
    int ox = blockIdx.y * 32 + threadIdx.x;
    int oy = blockIdx.x * 32;
#pragma unroll
    for (int j = 0; j < 32; j += 8) {
        float a = tb[threadIdx.x][threadIdx.y + j];
        uint32_t ua = __float_as_uint(a) & 0xFFFF0000u;
        long long idx = (long long)(oy + threadIdx.y + j) * 4096 + ox;
        ((uint16_t*)oh)[idx] = (uint16_t)(ua >> 16);
        ol[idx] = __float2bfloat16_rn(a - __uint_as_float(ua));
    }
}

// ---------------------------------------------------------------------------
// Row softmax over 4096 floats; writes split bf16 weights.
// ---------------------------------------------------------------------------
__global__ void __launch_bounds__(256)
softmax_split(const float* __restrict__ S, bf16* __restrict__ wh, bf16* __restrict__ wl)
{
    const float* row = S + (size_t)blockIdx.x * 4096u;
    const size_t ob = (size_t)blockIdx.x * 4096u;
    const int t = threadIdx.x, lane = t & 31, wid = t >> 5;
    __shared__ float red[8];

    float v[16];
    float m = -3.4e38f;
    const float4* r4 = (const float4*)row;
#pragma unroll
    for (int i = 0; i < 4; i++) {
        float4 val = r4[t + i * 256];
        v[4 * i + 0] = val.x; v[4 * i + 1] = val.y;
        v[4 * i + 2] = val.z; v[4 * i + 3] = val.w;
        m = fmaxf(m, fmaxf(fmaxf(val.x, val.y), fmaxf(val.z, val.w)));
    }
#pragma unroll
    for (int o = 16; o > 0; o >>= 1) m = fmaxf(m, __shfl_xor_sync(0xffffffffu, m, o));
    if (lane == 0) red[wid] = m;
    __syncthreads();
    if (t == 0) {
        float mm = red[0];
#pragma unroll
        for (int i = 1; i < 8; i++) mm = fmaxf(mm, red[i]);
        red[0] = mm;
    }
    __syncthreads();
    m = red[0];
    __syncthreads();

    float s = 0.f;
#pragma unroll
    for (int i = 0; i < 16; i++) { v[i] = __expf(v[i] - m); s += v[i]; }
#pragma unroll
    for (int o = 16; o > 0; o >>= 1) s += __shfl_xor_sync(0xffffffffu, s, o);
    if (lane == 0) red[wid] = s;
    __syncthreads();
    if (t == 0) {
        float ss = red[0];
#pragma unroll
        for (int i = 1; i < 8; i++) ss += red[i];
        red[0] = ss;
    }
    __syncthreads();
    float inv = 1.0f / red[0];

#pragma unroll
    for (int i = 0; i < 4; i++) {
        size_t base = ob + (size_t)(t + i * 256) * 4;
        uint32_t h2, l2;
        split2(v[4 * i + 0] * inv, v[4 * i + 1] * inv, h2, l2);
        *(uint32_t*)&wh[base]     = h2;
        *(uint32_t*)&wl[base]     = l2;
        split2(v[4 * i + 2] * inv, v[4 * i + 3] * inv, h2, l2);
        *(uint32_t*)&wh[base + 2] = h2;
        *(uint32_t*)&wl[base + 2] = l2;
    }
}

// ---------------------------------------------------------------------------
extern "C" void kernel_launch(void* const* d_in, const int* in_sizes, int n_in,
                              void* d_out, int out_size)
{
    const float* x  = (const float*)d_in[0];
    const float* Wq = (const float*)d_in[1];
    const float* bq = (const float*)d_in[2];
    const float* Wk = (const float*)d_in[3];
    const float* bk = (const float*)d_in[4];
    const float* Wv = (const float*)d_in[5];
    const float* bv = (const float*)d_in[6];
    const float* Wo = (const float*)d_in[7];
    const float* bo = (const float*)d_in[8];
    float* out = (float*)d_out;

    float *v, *s;
    bf16 *xh, *xl, *wqh, *wql, *wkh, *wkl, *wvh, *wvl, *woh, *wol;
    bf16 *qh, *ql, *kh, *kl, *vth, *vtl, *wh, *wl, *ah, *al;
    cudaGetSymbolAddress((void**)&v,   g_v);
    cudaGetSymbolAddress((void**)&s,   g_s);
    cudaGetSymbolAddress((void**)&xh,  g_xh);  cudaGetSymbolAddress((void**)&xl,  g_xl);
    cudaGetSymbolAddress((void**)&wqh, g_wqh); cudaGetSymbolAddress((void**)&wql, g_wql);
    cudaGetSymbolAddress((void**)&wkh, g_wkh); cudaGetSymbolAddress((void**)&wkl, g_wkl);
    cudaGetSymbolAddress((void**)&wvh, g_wvh); cudaGetSymbolAddress((void**)&wvl, g_wvl);
    cudaGetSymbolAddress((void**)&woh, g_woh); cudaGetSymbolAddress((void**)&wol, g_wol);
    cudaGetSymbolAddress((void**)&qh,  g_qh);  cudaGetSymbolAddress((void**)&ql,  g_ql);
    cudaGetSymbolAddress((void**)&kh,  g_kh);  cudaGetSymbolAddress((void**)&kl,  g_kl);
    cudaGetSymbolAddress((void**)&vth, g_vth); cudaGetSymbolAddress((void**)&vtl, g_vtl);
    cudaGetSymbolAddress((void**)&wh,  g_wh);  cudaGetSymbolAddress((void**)&wl,  g_wl);
    cudaGetSymbolAddress((void**)&ah,  g_ah);  cudaGetSymbolAddress((void**)&al,  g_al);

    cudaFuncSetAttribute(gemm_b3<true,  true >, cudaFuncAttributeMaxDynamicSharedMemorySize, GEMM_SMEM);
    cudaFuncSetAttribute(gemm_b3<true,  false>, cudaFuncAttributeMaxDynamicSharedMemorySize, GEMM_SMEM);
    cudaFuncSetAttribute(gemm_b3<false, true >, cudaFuncAttributeMaxDynamicSharedMemorySize, GEMM_SMEM);
    cudaFuncSetAttribute(gemm_b3<false, false>, cudaFuncAttributeMaxDynamicSharedMemorySize, GEMM_SMEM);

    const int B = 2, S = 4096, H = 1024;
    const long long qkv = (long long)S * H;
    const long long ss  = (long long)S * S;
    dim3 blk(256);

    // split inputs
    split_f32<<<(B * S * H / 4 + 255) / 256, blk>>>(x,  xh,  xl,  B * S * H / 4);
    split_f32<<<(H * H / 4 + 255) / 256, blk>>>(Wq, wqh, wql, H * H / 4);
    split_f32<<<(H * H / 4 + 255) / 256, blk>>>(Wk, wkh, wkl, H * H / 4);
    split_f32<<<(H * H / 4 + 255) / 256, blk>>>(Wv, wvh, wvl, H * H / 4);
    split_f32<<<(H * H / 4 + 255) / 256, blk>>>(Wo, woh, wol, H * H / 4);

    // Q/K projections -> split; V projection -> fp32 (for transpose)
    dim3 gProj(H / BN, (B * S) / BM, 1);
    gemm_b3<true, true ><<<gProj, blk, GEMM_SMEM>>>(xh, xl, wqh, wql, bq, nullptr, qh, ql,
                                                    B * S, H, H, 1.0f, 0, 0, 0);
    gemm_b3<true, true ><<<gProj, blk, GEMM_SMEM>>>(xh, xl, wkh, wkl, bk, nullptr, kh, kl,
                                                    B * S, H, H, 1.0f, 0, 0, 0);
    gemm_b3<true, false><<<gProj, blk, GEMM_SMEM>>>(xh, xl, wvh, wvl, bv, v, nullptr, nullptr,
                                                    B * S, H, H, 1.0f, 0, 0, 0);

    // scores = q @ k^T / 8 (fp32 out)
    dim3 gSc(S / BN, S / BM, B);
    gemm_b3<false, false><<<gSc, blk, GEMM_SMEM>>>(qh, ql, kh, kl, nullptr, s, nullptr, nullptr,
                                                   S, S, H, 0.125f, qkv, qkv, ss);

    // vT split
    dim3 gT(1024 / 32, 4096 / 32, B);
    transpose_v_split<<<gT, dim3(32, 8)>>>(v, vth, vtl);

    // softmax -> split weights
    softmax_split<<<B * S, blk>>>(s, wh, wl);

    // attn = weights @ vT^T -> split
    dim3 gAt(H / BN, S / BM, B);
    gemm_b3<false, true><<<gAt, blk, GEMM_SMEM>>>(wh, wl, vth, vtl, nullptr, nullptr, ah, al,
                                                  S, H, S, 1.0f, ss, qkv, qkv);

    // out = attn @ Wo^T + bo (fp32 out)
    gemm_b3<true, false><<<gProj, blk, GEMM_SMEM>>>(ah, al, woh, wol, bo, out, nullptr, nullptr,
                                                    B * S, H, H, 1.0f, 0, 0, 0);
}